// round 15
// baseline (speedup 1.0000x reference)
#include <cuda_runtime.h>
#include <cuda_fp16.h>
#include <math.h>

// Fixed problem shape
#define CW_ROW   128
#define NPTS     2048
#define NBATCH   512
#define MC_MULT  (4.0f / 2048.0f)
#define EPS_F    1e-9f

#define TPB       256
#define TILE_PTS  128                       // points per block (per warp)
#define NSPLIT    (NPTS / TILE_PTS)         // 16
#define GRID      ((NBATCH / 8) * NSPLIT)   // 1024
#define SSTR      9                         // stash stride in uint2 per point-slot

__device__ float        g_partials[GRID];
__device__ unsigned int g_count;            // zero-init; last block resets -> replay-safe

__device__ __forceinline__ __half2 ld_h2(const unsigned int& u) {
    return *reinterpret_cast<const __half2*>(&u);
}
__device__ __forceinline__ unsigned int h2_u(__half2 h) {
    return *reinterpret_cast<unsigned int*>(&h);
}

__global__ __launch_bounds__(TPB, 4)
void multibox_kernel(const float* __restrict__ cw,
                     const float* __restrict__ pts,
                     const int*   __restrict__ nf1,
                     float*       __restrict__ out)
{
    __shared__ __align__(16) unsigned int s_ph[TILE_PTS * 16]; // 8 KB: points as half2
    __shared__ __align__(16) uint2 s_stash[8 * 32 * SSTR];     // 18 KB margin stash
    __shared__ float s_red[TPB];
    __shared__ int   s_last;

    const int tid  = threadIdx.x;
    const int bid  = blockIdx.x;
    const int bg   = bid >> 4;      // batch group 0..63
    const int ts   = bid & 15;      // point-tile split 0..15

    const int w    = tid >> 5;      // warp -> batch within group
    const int lane = tid & 31;
    const int g    = lane >> 3;     // point sub-slot, 0..3
    const int j    = lane & 7;
    const int cl   = j >> 2;        // class: 0 -> c, 1 -> d
    const int qr   = j & 3;         // quarter: dims qr*8 .. qr*8+7

    // ---- convert this block's 128-point tile to half2 in smem ----
    const float4* __restrict__ src = (const float4*)pts + (long)ts * TILE_PTS * 8;
#pragma unroll
    for (int i = 0; i < 4; i++) {
        int f = tid + i * TPB;                 // float4 index, 0..1023
        float4 v = src[f];
        __half2 h0 = __floats2half2_rn(v.x, v.y);
        __half2 h1 = __floats2half2_rn(v.z, v.w);
        ((uint2*)s_ph)[f] = make_uint2(h2_u(h0), h2_u(h1));
    }

    // ---- this lane's params: both k-boxes of its class, its 8 dims (half2) ----
    const int batch = bg * 8 + w;
    const int cls   = nf1[2 * batch + cl];
    const float* row = cw + (long)cls * CW_ROW + qr * 8;

    __half2 c0[4], o0[4], c1[4], o1[4];
#pragma unroll
    for (int q = 0; q < 2; q++) {
        float4 cc0 = *(const float4*)(row +      q * 4);   // k0 center
        float4 oo0 = *(const float4*)(row + 32 + q * 4);   // k0 offset
        float4 cc1 = *(const float4*)(row + 64 + q * 4);   // k1 center
        float4 oo1 = *(const float4*)(row + 96 + q * 4);   // k1 offset
        c0[2*q+0] = __floats2half2_rn(cc0.x, cc0.y);
        c0[2*q+1] = __floats2half2_rn(cc0.z, cc0.w);
        o0[2*q+0] = __floats2half2_rn(fabsf(oo0.x), fabsf(oo0.y));
        o0[2*q+1] = __floats2half2_rn(fabsf(oo0.z), fabsf(oo0.w));
        c1[2*q+0] = __floats2half2_rn(cc1.x, cc1.y);
        c1[2*q+1] = __floats2half2_rn(cc1.z, cc1.w);
        o1[2*q+0] = __floats2half2_rn(fabsf(oo1.x), fabsf(oo1.y));
        o1[2*q+1] = __floats2half2_rn(fabsf(oo1.z), fabsf(oo1.w));
    }
    __syncthreads();

    uint2* wst = &s_stash[w * 32 * SSTR];
    float acc = 0.0f;

#pragma unroll 8
    for (int it = 0; it < TILE_PTS / 4; it++) {            // 32 iters, 4 points/warp
        // one LDS.128: this point's quarter (8 dims = 4 half2), 16B aligned
        const uint4 u = *(const uint4*)&s_ph[((it * 4 + g) * 4 + qr) * 4];
        __half2 p0 = ld_h2(u.x), p1 = ld_h2(u.y), p2 = ld_h2(u.z), p3 = ld_h2(u.w);

        // k0: margin2 = off - |p - c|, min over 4 half2
        __half2 x0 = __hsub2(o0[0], __habs2(__hsub2(p0, c0[0])));
        __half2 x1 = __hsub2(o0[1], __habs2(__hsub2(p1, c0[1])));
        __half2 x2 = __hsub2(o0[2], __habs2(__hsub2(p2, c0[2])));
        __half2 x3 = __hsub2(o0[3], __habs2(__hsub2(p3, c0[3])));
        __half2 mA = __hmin2(__hmin2(x0, x1), __hmin2(x2, x3));

        // k1
        __half2 y0 = __hsub2(o1[0], __habs2(__hsub2(p0, c1[0])));
        __half2 y1 = __hsub2(o1[1], __habs2(__hsub2(p1, c1[1])));
        __half2 y2 = __hsub2(o1[2], __habs2(__hsub2(p2, c1[2])));
        __half2 y3 = __hsub2(o1[3], __habs2(__hsub2(p3, c1[3])));
        __half2 mB = __hmin2(__hmin2(y0, y1), __hmin2(y2, y3));

        // one STS.64: (k0 partial half2, k1 partial half2)
        wst[((it & 7) * 4 + g) * SSTR + j] = make_uint2(h2_u(mA), h2_u(mB));

        if ((it & 7) == 7) {
            // bulk combine: lane p handles stashed point p (no shuffles)
            __syncwarp();
            const uint2* sp = &wst[lane * SSTR];
            uint2 a0 = sp[0], a1 = sp[1], a2 = sp[2], a3 = sp[3];
            __half2 kc0 = __hmin2(__hmin2(ld_h2(a0.x), ld_h2(a1.x)),
                                  __hmin2(ld_h2(a2.x), ld_h2(a3.x)));
            __half2 kc1 = __hmin2(__hmin2(ld_h2(a0.y), ld_h2(a1.y)),
                                  __hmin2(ld_h2(a2.y), ld_h2(a3.y)));
            float2 fc0 = __half22float2(kc0);
            float2 fc1 = __half22float2(kc1);
            float mc = fmaxf(fminf(fc0.x, fc0.y), fminf(fc1.x, fc1.y));
            uint2 b0 = sp[4], b1 = sp[5], b2 = sp[6], b3 = sp[7];
            __half2 kd0 = __hmin2(__hmin2(ld_h2(b0.x), ld_h2(b1.x)),
                                  __hmin2(ld_h2(b2.x), ld_h2(b3.x)));
            __half2 kd1 = __hmin2(__hmin2(ld_h2(b0.y), ld_h2(b1.y)),
                                  __hmin2(ld_h2(b2.y), ld_h2(b3.y)));
            float2 fd0 = __half22float2(kd0);
            float2 fd1 = __half22float2(kd1);
            float md = fmaxf(fminf(fd0.x, fd0.y), fminf(fd1.x, fd1.y));

            float ci  = __fdividef(1.0f, 1.0f + __expf(-mc));
            float di  = __fdividef(1.0f, 1.0f + __expf(-md));
            float a1e = fmaxf(ci - 0.5f, 0.0f) * MC_MULT;
            float ia  = fmaxf(0.5f * (ci + di) - 0.5f, 0.0f) * MC_MULT;
            acc += 1.0f - __fdividef(ia, a1e + EPS_F);
            __syncwarp();   // stash fully consumed before next batch overwrites
        }
    }

    // ---- deterministic fixed-tree block reduction ----
    s_red[tid] = acc;
    __syncthreads();
#pragma unroll
    for (int s = TPB / 2; s > 0; s >>= 1) {
        if (tid < s) s_red[tid] += s_red[tid + s];
        __syncthreads();
    }

    if (tid == 0) {
        g_partials[bid] = s_red[0];
        __threadfence();
        unsigned old = atomicAdd(&g_count, 1u);
        s_last = (old == GRID - 1);
    }
    __syncthreads();

    if (s_last) {
        double* sd = (double*)s_stash;   // reuse stash smem (16B aligned)
        double v = 0.0;
#pragma unroll
        for (int i = 0; i < GRID / TPB; i++)
            v += (double)__ldcg(&g_partials[tid + i * TPB]);
        sd[tid] = v;
        __syncthreads();
#pragma unroll
        for (int s = TPB / 2; s > 0; s >>= 1) {
            if (tid < s) sd[tid] += sd[tid + s];
            __syncthreads();
        }
        if (tid == 0) {
            double loss = sd[0] / ((double)NBATCH * (double)NPTS);
            out[0] = loss > 0.0 ? (float)loss : 0.0f;
            g_count = 0;
        }
    }
}

extern "C" void kernel_launch(void* const* d_in, const int* in_sizes, int n_in,
                              void* d_out, int out_size)
{
    const float* cw  = (const float*)d_in[0];  // [50000,128]
    const float* pts = (const float*)d_in[1];  // [2048,32]
    const int*   nf1 = (const int*)  d_in[2];  // [512,2]
    multibox_kernel<<<GRID, TPB>>>(cw, pts, nf1, (float*)d_out);
}

// round 16
// speedup vs baseline: 1.0015x; 1.0015x over previous
#include <cuda_runtime.h>
#include <cuda_fp16.h>
#include <math.h>

// Fixed problem shape
#define CW_ROW   128
#define NPTS     2048
#define NBATCH   512
#define EPS2MC   1.024e-6f                  // 2*EPS / MC_MULT = 2e-9 * 512
#define TPB       256
#define TILE_PTS  128                       // points per block (per warp)
#define NSPLIT    (NPTS / TILE_PTS)         // 16
#define GRID      ((NBATCH / 8) * NSPLIT)   // 1024
#define SSTR      10                        // stash stride in uint2 (80B, 16B-aligned)

__device__ float        g_partials[GRID];
__device__ unsigned int g_count;            // zero-init; last block resets -> replay-safe

__device__ __forceinline__ __half2 ld_h2(const unsigned int& u) {
    return *reinterpret_cast<const __half2*>(&u);
}
__device__ __forceinline__ unsigned int h2_u(__half2 h) {
    return *reinterpret_cast<unsigned int*>(&h);
}
__device__ __forceinline__ __half2 tanh2(__half2 x) {
    unsigned int r, a = h2_u(x);
    asm("tanh.approx.f16x2 %0, %1;" : "=r"(r) : "r"(a));
    return ld_h2(r);
}

__global__ __launch_bounds__(TPB, 4)
void multibox_kernel(const float* __restrict__ cw,
                     const float* __restrict__ pts,
                     const int*   __restrict__ nf1,
                     float*       __restrict__ out)
{
    __shared__ __align__(16) unsigned int s_ph[TILE_PTS * 16]; // 8 KB: points as half2
    __shared__ __align__(16) uint2 s_stash[8 * 32 * SSTR];     // 20 KB margin stash
    __shared__ float s_red[TPB];
    __shared__ int   s_last;

    const int tid  = threadIdx.x;
    const int bid  = blockIdx.x;
    const int bg   = bid >> 4;      // batch group 0..63
    const int ts   = bid & 15;      // point-tile split 0..15

    const int w    = tid >> 5;      // warp -> batch within group
    const int lane = tid & 31;
    const int g    = lane >> 3;     // point sub-slot, 0..3
    const int j    = lane & 7;
    const int cl   = j >> 2;        // class: 0 -> c, 1 -> d
    const int qr   = j & 3;         // quarter: dims qr*8 .. qr*8+7

    // ---- convert this block's 128-point tile to half2 in smem ----
    const float4* __restrict__ src = (const float4*)pts + (long)ts * TILE_PTS * 8;
#pragma unroll
    for (int i = 0; i < 4; i++) {
        int f = tid + i * TPB;                 // float4 index, 0..1023
        float4 v = src[f];
        __half2 h0 = __floats2half2_rn(v.x, v.y);
        __half2 h1 = __floats2half2_rn(v.z, v.w);
        ((uint2*)s_ph)[f] = make_uint2(h2_u(h0), h2_u(h1));
    }

    // ---- this lane's params: both k-boxes of its class, its 8 dims (half2) ----
    const int batch = bg * 8 + w;
    const int cls   = nf1[2 * batch + cl];
    const float* row = cw + (long)cls * CW_ROW + qr * 8;

    __half2 c0[4], o0[4], c1[4], o1[4];
#pragma unroll
    for (int q = 0; q < 2; q++) {
        float4 cc0 = *(const float4*)(row +      q * 4);   // k0 center
        float4 oo0 = *(const float4*)(row + 32 + q * 4);   // k0 offset
        float4 cc1 = *(const float4*)(row + 64 + q * 4);   // k1 center
        float4 oo1 = *(const float4*)(row + 96 + q * 4);   // k1 offset
        c0[2*q+0] = __floats2half2_rn(cc0.x, cc0.y);
        c0[2*q+1] = __floats2half2_rn(cc0.z, cc0.w);
        o0[2*q+0] = __floats2half2_rn(fabsf(oo0.x), fabsf(oo0.y));
        o0[2*q+1] = __floats2half2_rn(fabsf(oo0.z), fabsf(oo0.w));
        c1[2*q+0] = __floats2half2_rn(cc1.x, cc1.y);
        c1[2*q+1] = __floats2half2_rn(cc1.z, cc1.w);
        o1[2*q+0] = __floats2half2_rn(fabsf(oo1.x), fabsf(oo1.y));
        o1[2*q+1] = __floats2half2_rn(fabsf(oo1.z), fabsf(oo1.w));
    }
    __syncthreads();

    uint2* wst = &s_stash[w * 32 * SSTR];
    float acc = 0.0f;
    const __half2 half_h2 = __floats2half2_rn(0.5f, 0.5f);

#pragma unroll 8
    for (int it = 0; it < TILE_PTS / 4; it++) {            // 32 iters, 4 points/warp
        // one LDS.128: this point's quarter (8 dims = 4 half2), 16B aligned
        const uint4 u = *(const uint4*)&s_ph[((it * 4 + g) * 4 + qr) * 4];
        __half2 p0 = ld_h2(u.x), p1 = ld_h2(u.y), p2 = ld_h2(u.z), p3 = ld_h2(u.w);

        // k0: margin2 = off - |p - c|, min over 4 half2
        __half2 x0 = __hsub2(o0[0], __habs2(__hsub2(p0, c0[0])));
        __half2 x1 = __hsub2(o0[1], __habs2(__hsub2(p1, c0[1])));
        __half2 x2 = __hsub2(o0[2], __habs2(__hsub2(p2, c0[2])));
        __half2 x3 = __hsub2(o0[3], __habs2(__hsub2(p3, c0[3])));
        __half2 mA = __hmin2(__hmin2(x0, x1), __hmin2(x2, x3));

        // k1
        __half2 y0 = __hsub2(o1[0], __habs2(__hsub2(p0, c1[0])));
        __half2 y1 = __hsub2(o1[1], __habs2(__hsub2(p1, c1[1])));
        __half2 y2 = __hsub2(o1[2], __habs2(__hsub2(p2, c1[2])));
        __half2 y3 = __hsub2(o1[3], __habs2(__hsub2(p3, c1[3])));
        __half2 mB = __hmin2(__hmin2(y0, y1), __hmin2(y2, y3));

        // one STS.64: (k0 partial half2, k1 partial half2)
        wst[((it & 7) * 4 + g) * SSTR + j] = make_uint2(h2_u(mA), h2_u(mB));

        if ((it & 7) == 7) {
            // bulk combine: lane p handles stashed point p (no shuffles)
            __syncwarp();
            const uint4* sp = (const uint4*)&wst[lane * SSTR];  // 16B aligned (SSTR=10)
            uint4 A = sp[0], B = sp[1];   // class c: (k0,k1) x quarters 0..3
            uint4 C = sp[2], D = sp[3];   // class d
            __half2 kc0 = __hmin2(__hmin2(ld_h2(A.x), ld_h2(A.z)),
                                  __hmin2(ld_h2(B.x), ld_h2(B.z)));
            __half2 kc1 = __hmin2(__hmin2(ld_h2(A.y), ld_h2(A.w)),
                                  __hmin2(ld_h2(B.y), ld_h2(B.w)));
            __half2 kd0 = __hmin2(__hmin2(ld_h2(C.x), ld_h2(C.z)),
                                  __hmin2(ld_h2(D.x), ld_h2(D.z)));
            __half2 kd1 = __hmin2(__hmin2(ld_h2(C.y), ld_h2(C.w)),
                                  __hmin2(ld_h2(D.y), ld_h2(D.w)));

            // horizontal reduce in half domain via lane swizzles:
            // cmin = (min kc0.xy, min kc1.xy), dmin = (min kd0.xy, min kd1.xy)
            __half2 cmin = __hmin2(__lows2half2(kc0, kc1), __highs2half2(kc0, kc1));
            __half2 dmin = __hmin2(__lows2half2(kd0, kd1), __highs2half2(kd0, kd1));
            // M = (max over k for class c, max over k for class d) = (mc, md)
            __half2 M = __hmax2(__lows2half2(cmin, dmin), __highs2half2(cmin, dmin));

            // sigmoid(m)-0.5 = 0.5*tanh(m/2): one tanh.f16x2 for both classes
            __half2 T = tanh2(__hmul2(M, half_h2));
            float2 f = __half22float2(T);
            float num = fmaxf(f.x + f.y, 0.0f);          // ~ 4*ia/MC
            float den = fmaxf(f.x, 0.0f) + EPS2MC;       // ~ 2*a1/MC + 2eps/MC
            acc += 1.0f - 0.5f * __fdividef(num, den);
            __syncwarp();   // stash fully consumed before next batch overwrites
        }
    }

    // ---- deterministic fixed-tree block reduction ----
    s_red[tid] = acc;
    __syncthreads();
#pragma unroll
    for (int s = TPB / 2; s > 0; s >>= 1) {
        if (tid < s) s_red[tid] += s_red[tid + s];
        __syncthreads();
    }

    if (tid == 0) {
        g_partials[bid] = s_red[0];
        __threadfence();
        unsigned old = atomicAdd(&g_count, 1u);
        s_last = (old == GRID - 1);
    }
    __syncthreads();

    if (s_last) {
        double* sd = (double*)s_stash;   // reuse stash smem (16B aligned)
        double v = 0.0;
#pragma unroll
        for (int i = 0; i < GRID / TPB; i++)
            v += (double)__ldcg(&g_partials[tid + i * TPB]);
        sd[tid] = v;
        __syncthreads();
#pragma unroll
        for (int s = TPB / 2; s > 0; s >>= 1) {
            if (tid < s) sd[tid] += sd[tid + s];
            __syncthreads();
        }
        if (tid == 0) {
            double loss = sd[0] / ((double)NBATCH * (double)NPTS);
            out[0] = loss > 0.0 ? (float)loss : 0.0f;
            g_count = 0;
        }
    }
}

extern "C" void kernel_launch(void* const* d_in, const int* in_sizes, int n_in,
                              void* d_out, int out_size)
{
    const float* cw  = (const float*)d_in[0];  // [50000,128]
    const float* pts = (const float*)d_in[1];  // [2048,32]
    const int*   nf1 = (const int*)  d_in[2];  // [512,2]
    multibox_kernel<<<GRID, TPB>>>(cw, pts, nf1, (float*)d_out);
}

// round 17
// speedup vs baseline: 1.0327x; 1.0312x over previous
#include <cuda_runtime.h>
#include <cuda_fp16.h>
#include <math.h>

// Fixed problem shape
#define CW_ROW   128
#define NPTS     2048
#define NBATCH   512
#define EPS2MC   1.024e-6f                  // 2*EPS / MC_MULT
#define TPB       256
#define TILE_PTS  128                       // points per block (per warp)
#define NSPLIT    (NPTS / TILE_PTS)         // 16
#define GRID      ((NBATCH / 8) * NSPLIT)   // 1024
#define SSTR      10                        // stash stride in uint2 (80B, 16B-aligned)

__device__ float        g_partials[GRID];
__device__ unsigned int g_count;            // zero-init; last block resets -> replay-safe

__device__ __forceinline__ __half2 ld_h2(const unsigned int& u) {
    return *reinterpret_cast<const __half2*>(&u);
}
__device__ __forceinline__ unsigned int h2_u(__half2 h) {
    return *reinterpret_cast<unsigned int*>(&h);
}
__device__ __forceinline__ __half2 tanh2(__half2 x) {
    unsigned int r, a = h2_u(x);
    asm("tanh.approx.f16x2 %0, %1;" : "=r"(r) : "r"(a));
    return ld_h2(r);
}

__global__ __launch_bounds__(TPB, 4)
void multibox_kernel(const float* __restrict__ cw,
                     const float* __restrict__ pts,
                     const int*   __restrict__ nf1,
                     float*       __restrict__ out)
{
    __shared__ __align__(16) unsigned int s_ph[TILE_PTS * 16]; // 8 KB: points as half2
    __shared__ __align__(16) uint2 s_stash[8 * 32 * SSTR];     // 20 KB margin stash
    __shared__ float s_red[8];
    __shared__ int   s_last;

    const int tid  = threadIdx.x;
    const int bid  = blockIdx.x;
    const int bg   = bid >> 4;      // batch group 0..63
    const int ts   = bid & 15;      // point-tile split 0..15

    const int w    = tid >> 5;      // warp -> batch within group
    const int lane = tid & 31;
    const int g    = lane >> 3;     // point sub-slot, 0..3
    const int j    = lane & 7;
    const int cl   = j >> 2;        // class: 0 -> c, 1 -> d
    const int qr   = j & 3;         // quarter: dims qr*8 .. qr*8+7

    // ---- convert this block's 128-point tile to half2 in smem ----
    const float4* __restrict__ src = (const float4*)pts + (long)ts * TILE_PTS * 8;
#pragma unroll
    for (int i = 0; i < 4; i++) {
        int f = tid + i * TPB;                 // float4 index, 0..1023
        float4 v = src[f];
        __half2 h0 = __floats2half2_rn(v.x, v.y);
        __half2 h1 = __floats2half2_rn(v.z, v.w);
        ((uint2*)s_ph)[f] = make_uint2(h2_u(h0), h2_u(h1));
    }

    // ---- this lane's params: both k-boxes of its class, its 8 dims (half2) ----
    const int batch = bg * 8 + w;
    const int cls   = nf1[2 * batch + cl];
    const float* row = cw + (long)cls * CW_ROW + qr * 8;

    __half2 c0[4], o0[4], c1[4], o1[4];
#pragma unroll
    for (int q = 0; q < 2; q++) {
        float4 cc0 = *(const float4*)(row +      q * 4);   // k0 center
        float4 oo0 = *(const float4*)(row + 32 + q * 4);   // k0 offset
        float4 cc1 = *(const float4*)(row + 64 + q * 4);   // k1 center
        float4 oo1 = *(const float4*)(row + 96 + q * 4);   // k1 offset
        c0[2*q+0] = __floats2half2_rn(cc0.x, cc0.y);
        c0[2*q+1] = __floats2half2_rn(cc0.z, cc0.w);
        o0[2*q+0] = __floats2half2_rn(fabsf(oo0.x), fabsf(oo0.y));
        o0[2*q+1] = __floats2half2_rn(fabsf(oo0.z), fabsf(oo0.w));
        c1[2*q+0] = __floats2half2_rn(cc1.x, cc1.y);
        c1[2*q+1] = __floats2half2_rn(cc1.z, cc1.w);
        o1[2*q+0] = __floats2half2_rn(fabsf(oo1.x), fabsf(oo1.y));
        o1[2*q+1] = __floats2half2_rn(fabsf(oo1.z), fabsf(oo1.w));
    }
    __syncthreads();

    uint2* wst = &s_stash[w * 32 * SSTR];
    float acc = 0.0f;
    const __half2 half_h2 = __floats2half2_rn(0.5f, 0.5f);

#pragma unroll 8
    for (int it = 0; it < TILE_PTS / 4; it++) {            // 32 iters, 4 points/warp
        // one LDS.128: this point's quarter (8 dims = 4 half2), 16B aligned
        const uint4 u = *(const uint4*)&s_ph[((it * 4 + g) * 4 + qr) * 4];
        __half2 p0 = ld_h2(u.x), p1 = ld_h2(u.y), p2 = ld_h2(u.z), p3 = ld_h2(u.w);

        // k0: margin2 = off - |p - c|, min over 4 half2
        __half2 x0 = __hsub2(o0[0], __habs2(__hsub2(p0, c0[0])));
        __half2 x1 = __hsub2(o0[1], __habs2(__hsub2(p1, c0[1])));
        __half2 x2 = __hsub2(o0[2], __habs2(__hsub2(p2, c0[2])));
        __half2 x3 = __hsub2(o0[3], __habs2(__hsub2(p3, c0[3])));
        __half2 mA = __hmin2(__hmin2(x0, x1), __hmin2(x2, x3));

        // k1
        __half2 y0 = __hsub2(o1[0], __habs2(__hsub2(p0, c1[0])));
        __half2 y1 = __hsub2(o1[1], __habs2(__hsub2(p1, c1[1])));
        __half2 y2 = __hsub2(o1[2], __habs2(__hsub2(p2, c1[2])));
        __half2 y3 = __hsub2(o1[3], __habs2(__hsub2(p3, c1[3])));
        __half2 mB = __hmin2(__hmin2(y0, y1), __hmin2(y2, y3));

        // one STS.64: (k0 partial half2, k1 partial half2)
        wst[((it & 7) * 4 + g) * SSTR + j] = make_uint2(h2_u(mA), h2_u(mB));

        if ((it & 7) == 7) {
            // bulk combine: lane p handles stashed point p (no shuffles)
            __syncwarp();
            const uint4* sp = (const uint4*)&wst[lane * SSTR];  // 16B aligned (SSTR=10)
            uint4 A = sp[0], B = sp[1];   // class c: (k0,k1) x quarters 0..3
            uint4 C = sp[2], D = sp[3];   // class d
            __half2 kc0 = __hmin2(__hmin2(ld_h2(A.x), ld_h2(A.z)),
                                  __hmin2(ld_h2(B.x), ld_h2(B.z)));
            __half2 kc1 = __hmin2(__hmin2(ld_h2(A.y), ld_h2(A.w)),
                                  __hmin2(ld_h2(B.y), ld_h2(B.w)));
            __half2 kd0 = __hmin2(__hmin2(ld_h2(C.x), ld_h2(C.z)),
                                  __hmin2(ld_h2(D.x), ld_h2(D.z)));
            __half2 kd1 = __hmin2(__hmin2(ld_h2(C.y), ld_h2(C.w)),
                                  __hmin2(ld_h2(D.y), ld_h2(D.w)));

            // horizontal reduce in half domain via lane swizzles
            __half2 cmin = __hmin2(__lows2half2(kc0, kc1), __highs2half2(kc0, kc1));
            __half2 dmin = __hmin2(__lows2half2(kd0, kd1), __highs2half2(kd0, kd1));
            __half2 M = __hmax2(__lows2half2(cmin, dmin), __highs2half2(cmin, dmin));

            // sigmoid(m)-0.5 = 0.5*tanh(m/2): one tanh.f16x2 for both classes
            __half2 T = tanh2(__hmul2(M, half_h2));
            float2 f = __half22float2(T);
            float num = fmaxf(f.x + f.y, 0.0f);
            float den = fmaxf(f.x, 0.0f) + EPS2MC;
            acc += 1.0f - 0.5f * __fdividef(num, den);
            __syncwarp();   // stash fully consumed before next batch overwrites
        }
    }

    // ---- deterministic warp-butterfly reduction (no block barriers) ----
#pragma unroll
    for (int s = 16; s > 0; s >>= 1)
        acc += __shfl_xor_sync(0xFFFFFFFFu, acc, s);   // fixed xor tree -> deterministic
    if (lane == 0) s_red[w] = acc;
    __syncthreads();   // single block barrier

    if (tid == 0) {
        float v = 0.0f;
#pragma unroll
        for (int i = 0; i < 8; i++) v += s_red[i];     // fixed order
        g_partials[bid] = v;
        __threadfence();
        unsigned old = atomicAdd(&g_count, 1u);
        s_last = (old == GRID - 1);
    }
    __syncthreads();

    if (s_last) {
        double* sd = (double*)s_stash;   // reuse stash smem (16B aligned)
        double v = 0.0;
#pragma unroll
        for (int i = 0; i < GRID / TPB; i++)
            v += (double)__ldcg(&g_partials[tid + i * TPB]);
        sd[tid] = v;
        __syncthreads();
#pragma unroll
        for (int s = TPB / 2; s > 0; s >>= 1) {
            if (tid < s) sd[tid] += sd[tid + s];
            __syncthreads();
        }
        if (tid == 0) {
            double loss = sd[0] / ((double)NBATCH * (double)NPTS);
            out[0] = loss > 0.0 ? (float)loss : 0.0f;
            g_count = 0;
        }
    }
}

extern "C" void kernel_launch(void* const* d_in, const int* in_sizes, int n_in,
                              void* d_out, int out_size)
{
    const float* cw  = (const float*)d_in[0];  // [50000,128]
    const float* pts = (const float*)d_in[1];  // [2048,32]
    const int*   nf1 = (const int*)  d_in[2];  // [512,2]
    multibox_kernel<<<GRID, TPB>>>(cw, pts, nf1, (float*)d_out);
}